// round 3
// baseline (speedup 1.0000x reference)
#include <cuda_runtime.h>
#include <float.h>
#include <stdint.h>

// Problem constants
#define PN 32768   // points per side
#define PM 8192    // shortcut (query) points per side
#define PC 256     // feature channels

#define TS 2048          // tile points in smem
#define WARPS 4          // warps per block
#define QPW 4            // queries per warp
#define BLOCK (WARPS * 32)
#define QPB (WARPS * QPW)   // 16 queries per block

// Pre-packed SoA coordinate scratch (b2 computed once; shared by main loop + rescan)
__device__ float g_px[2][PN];
__device__ float g_py[2][PN];
__device__ float g_pz[2][PN];
__device__ float g_pb2[2][PN];

__forceinline__ __device__ float sqnorm3(float x, float y, float z) {
    return (x * x + y * y) + z * z;
}

// Scalar distance — must be bit-identical to the packed f32x2 path (it is: IEEE per-component).
__forceinline__ __device__ float dist_d(float x, float y, float z, float b2,
                                        float qx, float qy, float qz, float a2) {
    const float dot = fmaf(x, qx, fmaf(y, qy, z * qz));
    const float t   = a2 + b2;
    return fmaf(-2.0f, dot, t);
}

// Packed f32x2 ops (sm_103a): two independent fp32 lanes per instruction.
#define FMA2(r, a, b, c) asm("fma.rn.f32x2 %0, %1, %2, %3;" : "=l"(r) : "l"(a), "l"(b), "l"(c))
#define MUL2(r, a, b)    asm("mul.rn.f32x2 %0, %1, %2;"     : "=l"(r) : "l"(a), "l"(b))
#define ADD2(r, a, b)    asm("add.rn.f32x2 %0, %1, %2;"     : "=l"(r) : "l"(a), "l"(b))
#define PACK2(r, lo, hi) asm("mov.b64 %0, {%1, %2};" : "=l"(r) : "f"(lo), "f"(hi))
#define UNPACK2(lo, hi, r) asm("mov.b64 {%0, %1}, %2;" : "=f"(lo), "=f"(hi) : "l"(r))

// lexicographic (d, i) strict less-than
__forceinline__ __device__ bool lex_lt(float da, int ia, float db, int ib) {
    return (da < db) || (da == db && ia < ib);
}

__global__ void pack_kernel(const float* __restrict__ src_coords,
                            const float* __restrict__ tgt_coords) {
    const int n = blockIdx.x * blockDim.x + threadIdx.x;
    const int side = blockIdx.y;
    const float* __restrict__ c = side ? tgt_coords : src_coords;
    const float x = c[n * 3 + 0];
    const float y = c[n * 3 + 1];
    const float z = c[n * 3 + 2];
    g_px[side][n]  = x;
    g_py[side][n]  = y;
    g_pz[side][n]  = z;
    g_pb2[side][n] = sqnorm3(x, y, z);
}

__global__ __launch_bounds__(BLOCK) void closest_pool_main(
    const float* __restrict__ src_feats,
    const float* __restrict__ tgt_feats,
    const float* __restrict__ src_sc,
    const float* __restrict__ tgt_sc,
    float* __restrict__ out)
{
    __shared__ __align__(16) float tx[TS];
    __shared__ __align__(16) float ty[TS];
    __shared__ __align__(16) float tz[TS];
    __shared__ __align__(16) float tb2[TS];

    const int side = blockIdx.y;
    const float* __restrict__ feats = side ? tgt_feats : src_feats;
    const float* __restrict__ qc    = side ? tgt_sc    : src_sc;
    float* __restrict__ out_side = out + (size_t)side * PM * PC;

    const float* __restrict__ gx  = g_px[side];
    const float* __restrict__ gy  = g_py[side];
    const float* __restrict__ gz  = g_pz[side];
    const float* __restrict__ gb2 = g_pb2[side];

    const int warp = threadIdx.x >> 5;
    const int lane = threadIdx.x & 31;
    const int qbase = blockIdx.x * QPB + warp * QPW;

    // Per-warp queries: scalar + packed broadcast copies
    float qx[QPW], qy[QPW], qz[QPW], qa2[QPW];
    unsigned long long qx2[QPW], qy2[QPW], qz2[QPW], qa22[QPW];
    #pragma unroll
    for (int q = 0; q < QPW; q++) {
        const int qi = qbase + q;
        qx[q] = qc[qi * 3 + 0];
        qy[q] = qc[qi * 3 + 1];
        qz[q] = qc[qi * 3 + 2];
        qa2[q] = sqnorm3(qx[q], qy[q], qz[q]);
        PACK2(qx2[q], qx[q], qx[q]);
        PACK2(qy2[q], qy[q], qy[q]);
        PACK2(qz2[q], qz[q], qz[q]);
        PACK2(qa22[q], qa2[q], qa2[q]);
    }
    unsigned long long NEG2;
    { const float m2 = -2.0f; PACK2(NEG2, m2, m2); }

    // Per-lane top-1 per query (strict '<' keeps earliest index; per-lane visit order is ascending n)
    float d1[QPW];
    int   i1[QPW];
    #pragma unroll
    for (int q = 0; q < QPW; q++) { d1[q] = FLT_MAX; i1[q] = 0x7fffffff; }

    for (int base = 0; base < PN; base += TS) {
        __syncthreads();
        // Vectorized SoA tile fill: float4 copies, fully coalesced.
        {
            const int nf4 = base >> 2;
            const float4* __restrict__ g4x  = (const float4*)gx  + nf4;
            const float4* __restrict__ g4y  = (const float4*)gy  + nf4;
            const float4* __restrict__ g4z  = (const float4*)gz  + nf4;
            const float4* __restrict__ g4b2 = (const float4*)gb2 + nf4;
            #pragma unroll
            for (int t = threadIdx.x; t < TS / 4; t += BLOCK) {
                ((float4*)tx)[t]  = g4x[t];
                ((float4*)ty)[t]  = g4y[t];
                ((float4*)tz)[t]  = g4z[t];
                ((float4*)tb2)[t] = g4b2[t];
            }
        }
        __syncthreads();

        // Each lane handles point pairs j = 64u + 2*lane (+0/+1)
        #pragma unroll 4
        for (int u = 0; u < TS / 64; u++) {
            const int j = u * 64 + 2 * lane;
            const unsigned long long xp  = *(const unsigned long long*)&tx[j];
            const unsigned long long yp  = *(const unsigned long long*)&ty[j];
            const unsigned long long zp  = *(const unsigned long long*)&tz[j];
            const unsigned long long b2p = *(const unsigned long long*)&tb2[j];
            const int n0 = base + j;
            #pragma unroll
            for (int q = 0; q < QPW; q++) {
                unsigned long long acc, dot2, d2v;
                MUL2(acc, zp, qz2[q]);
                FMA2(dot2, yp, qy2[q], acc);
                FMA2(dot2, xp, qx2[q], dot2);
                ADD2(acc, qa22[q], b2p);
                FMA2(d2v, NEG2, dot2, acc);
                float dlo, dhi;
                UNPACK2(dlo, dhi, d2v);
                // lo (smaller n) first — preserves stability
                if (dlo < d1[q]) { d1[q] = dlo; i1[q] = n0; }
                if (dhi < d1[q]) { d1[q] = dhi; i1[q] = n0 + 1; }
            }
        }
    }

    // ---- Epilogue per query ----
    #pragma unroll 1
    for (int q = 0; q < QPW; q++) {
        // 1) warp top-2 over the 32 lane minima, lexicographic (d, i)
        float bd = d1[q], sd = FLT_MAX;
        int   bi = i1[q], si = 0x7fffffff;
        #pragma unroll
        for (int off = 16; off > 0; off >>= 1) {
            const float obd = __shfl_xor_sync(0xFFFFFFFFu, bd, off);
            const float osd = __shfl_xor_sync(0xFFFFFFFFu, sd, off);
            const int   obi = __shfl_xor_sync(0xFFFFFFFFu, bi, off);
            const int   osi = __shfl_xor_sync(0xFFFFFFFFu, si, off);
            const bool aFirst = lex_lt(bd, bi, obd, obi);
            const float c1 = aFirst ? obd : bd;  const int c1i = aFirst ? obi : bi;
            const float c2 = aFirst ? sd  : osd; const int c2i = aFirst ? si  : osi;
            const float nb = aFirst ? bd  : obd; const int nbi = aFirst ? bi  : obi;
            const bool t1 = lex_lt(c1, c1i, c2, c2i);
            bd = nb; bi = nbi;
            sd = t1 ? c1 : c2; si = t1 ? c1i : c2i;
        }
        bd = __shfl_sync(0xFFFFFFFFu, bd, 0);
        bi = __shfl_sync(0xFFFFFFFFu, bi, 0);
        sd = __shfl_sync(0xFFFFFFFFu, sd, 0);
        si = __shfl_sync(0xFFFFFFFFu, si, 0);

        // 2) cooperative rescan of the winning lane's subset:
        //    winner lane processed all n with (n mod 64) in {slot, slot+1}
        const int slot = bi & 62;
        float p1d = FLT_MAX, p2d = FLT_MAX;
        int   p1i = 0x7fffffff, p2i = 0x7fffffff;
        #pragma unroll 4
        for (int r = 0; r < PN / 64 / 32; r++) {       // 16 iterations
            const int m  = lane + 32 * r;
            const int n0 = 64 * m + slot;
            #pragma unroll
            for (int h = 0; h < 2; h++) {
                const int n = n0 + h;
                const float d = dist_d(gx[n], gy[n], gz[n], gb2[n],
                                       qx[q], qy[q], qz[q], qa2[q]);
                const bool lt1 = d < p1d;
                const bool lt2 = d < p2d;
                p2d = lt1 ? p1d : (lt2 ? d : p2d);
                p2i = lt1 ? p1i : (lt2 ? n : p2i);
                p1d = lt1 ? d   : p1d;
                p1i = lt1 ? n   : p1i;
            }
        }
        // merge lane top-2 lists (lexicographic)
        #pragma unroll
        for (int off = 16; off > 0; off >>= 1) {
            const float o1d = __shfl_xor_sync(0xFFFFFFFFu, p1d, off);
            const float o2d = __shfl_xor_sync(0xFFFFFFFFu, p2d, off);
            const int   o1i = __shfl_xor_sync(0xFFFFFFFFu, p1i, off);
            const int   o2i = __shfl_xor_sync(0xFFFFFFFFu, p2i, off);
            const bool aFirst = lex_lt(p1d, p1i, o1d, o1i);
            const float c1 = aFirst ? o1d : p1d;  const int c1i = aFirst ? o1i : p1i;
            const float c2 = aFirst ? p2d : o2d;  const int c2i = aFirst ? p2i : o2i;
            const float nb = aFirst ? p1d : o1d;  const int nbi = aFirst ? p1i : o1i;
            const bool t1 = lex_lt(c1, c1i, c2, c2i);
            p1d = nb; p1i = nbi;
            p2d = t1 ? c1 : c2; p2i = t1 ? c1i : c2i;
        }
        float wsd = __shfl_sync(0xFFFFFFFFu, p2d, 0);   // winner-subset second
        int   wsi = __shfl_sync(0xFFFFFFFFu, p2i, 0);

        // 3) global 2nd-nearest = lexmin(winner-subset 2nd, best-of-other-lanes)
        const int sel = lex_lt(wsd, wsi, sd, si) ? wsi : si;

        // 4) gather feature row (256 floats), warp-coalesced
        const float4* __restrict__ srow = reinterpret_cast<const float4*>(feats + (size_t)sel * PC);
        float4* __restrict__ drow = reinterpret_cast<float4*>(out_side + (size_t)(qbase + q) * PC);
        #pragma unroll
        for (int k = lane; k < PC / 4; k += 32) {
            drow[k] = srow[k];
        }
    }
}

extern "C" void kernel_launch(void* const* d_in, const int* in_sizes, int n_in,
                              void* d_out, int out_size)
{
    const float* src        = (const float*)d_in[0];
    const float* tgt        = (const float*)d_in[1];
    const float* src_coords = (const float*)d_in[2];
    const float* tgt_coords = (const float*)d_in[3];
    const float* src_sc     = (const float*)d_in[4];
    const float* tgt_sc     = (const float*)d_in[5];
    float* out = (float*)d_out;

    dim3 pgrid(PN / 256, 2);
    pack_kernel<<<pgrid, 256>>>(src_coords, tgt_coords);

    dim3 grid(PM / QPB, 2);
    closest_pool_main<<<grid, BLOCK>>>(src, tgt, src_sc, tgt_sc, out);
}

// round 8
// speedup vs baseline: 2.0270x; 2.0270x over previous
#include <cuda_runtime.h>
#include <float.h>
#include <stdint.h>

// Problem constants
#define PN 32768   // points per side
#define PM 8192    // shortcut (query) points per side
#define PC 256     // feature channels

#define TS 2048          // tile points in smem
#define NT (PN / TS)     // 16 tiles
#define WARPS 8
#define QPW 4            // queries per warp
#define BLOCK (WARPS * 32)
#define QPB (WARPS * QPW)   // 32 queries per block

// Pre-packed SoA coordinates (b2 computed once; shared by main loop + rescan)
__device__ float g_px[2][PN];
__device__ float g_py[2][PN];
__device__ float g_pz[2][PN];
__device__ float g_pb2[2][PN];

__forceinline__ __device__ float sqnorm3(float x, float y, float z) {
    return (x * x + y * y) + z * z;
}

// Scalar distance — bit-identical to the packed f32x2 path (IEEE per-component),
// and to the R1 kernel that measured rel_err == 0.0 vs the reference.
__forceinline__ __device__ float dist_d(float x, float y, float z, float b2,
                                        float qx, float qy, float qz, float a2) {
    const float dot = fmaf(x, qx, fmaf(y, qy, z * qz));
    const float t   = a2 + b2;
    return fmaf(-2.0f, dot, t);
}

// Packed f32x2 ops (sm_103a)
#define FMA2(r, a, b, c) asm("fma.rn.f32x2 %0, %1, %2, %3;" : "=l"(r) : "l"(a), "l"(b), "l"(c))
#define MUL2(r, a, b)    asm("mul.rn.f32x2 %0, %1, %2;"     : "=l"(r) : "l"(a), "l"(b))
#define ADD2(r, a, b)    asm("add.rn.f32x2 %0, %1, %2;"     : "=l"(r) : "l"(a), "l"(b))
#define PACK2(r, lo, hi) asm("mov.b64 %0, {%1, %2};" : "=l"(r) : "f"(lo), "f"(hi))
#define UNPACK2(lo, hi, r) asm("mov.b64 {%0, %1}, %2;" : "=f"(lo), "=f"(hi) : "l"(r))

__forceinline__ __device__ bool lex_lt(float da, int ia, float db, int ib) {
    return (da < db) || (da == db && ia < ib);
}

__global__ void pack_kernel(const float* __restrict__ src_coords,
                            const float* __restrict__ tgt_coords) {
    const int n = blockIdx.x * blockDim.x + threadIdx.x;
    const int side = blockIdx.y;
    const float* __restrict__ c = side ? tgt_coords : src_coords;
    const float x = c[n * 3 + 0];
    const float y = c[n * 3 + 1];
    const float z = c[n * 3 + 2];
    g_px[side][n]  = x;
    g_py[side][n]  = y;
    g_pz[side][n]  = z;
    g_pb2[side][n] = sqnorm3(x, y, z);
}

__global__ __launch_bounds__(BLOCK, 4) void closest_pool_main(
    const float* __restrict__ src_feats,
    const float* __restrict__ tgt_feats,
    const float* __restrict__ src_sc,
    const float* __restrict__ tgt_sc,
    float* __restrict__ out)
{
    // Tiles stored as float2, chunk-contiguous with per-chunk rotation swizzle:
    // logical (chunk c, pair p) -> physical c*32 + ((p + c) & 31).
    __shared__ __align__(16) float2 shX[TS / 2];
    __shared__ __align__(16) float2 shY[TS / 2];
    __shared__ __align__(16) float2 shZ[TS / 2];
    __shared__ __align__(16) float2 shB[TS / 2];

    const int side = blockIdx.y;
    const float* __restrict__ feats = side ? tgt_feats : src_feats;
    const float* __restrict__ qc    = side ? tgt_sc    : src_sc;
    float* __restrict__ out_side = out + (size_t)side * PM * PC;

    const float* __restrict__ gx  = g_px[side];
    const float* __restrict__ gy  = g_py[side];
    const float* __restrict__ gz  = g_pz[side];
    const float* __restrict__ gb2 = g_pb2[side];

    const int warp = threadIdx.x >> 5;
    const int lane = threadIdx.x & 31;
    const int qbase = blockIdx.x * QPB + warp * QPW;

    // Packed query broadcasts only (scalars reloaded in epilogue to save regs)
    unsigned long long qx2[QPW], qy2[QPW], qz2[QPW], qa22[QPW];
    #pragma unroll
    for (int q = 0; q < QPW; q++) {
        const int qi = qbase + q;
        const float qx = qc[qi * 3 + 0];
        const float qy = qc[qi * 3 + 1];
        const float qz = qc[qi * 3 + 2];
        const float a2 = sqnorm3(qx, qy, qz);
        PACK2(qx2[q], qx, qx);
        PACK2(qy2[q], qy, qy);
        PACK2(qz2[q], qz, qz);
        PACK2(qa22[q], a2, a2);
    }
    unsigned long long NEG2;
    { const float m2 = -2.0f; PACK2(NEG2, m2, m2); }

    // Value-only per-lane minima (order-independent; indices recovered in epilogue)
    float dlo1[QPW], dhi1[QPW];
    #pragma unroll
    for (int q = 0; q < QPW; q++) { dlo1[q] = FLT_MAX; dhi1[q] = FLT_MAX; }

    for (int base = 0; base < PN; base += TS) {
        __syncthreads();
        // Fill: coalesced float4 global reads, swizzled float2 stores.
        {
            const float4* __restrict__ g4x = (const float4*)gx  + (base >> 2);
            const float4* __restrict__ g4y = (const float4*)gy  + (base >> 2);
            const float4* __restrict__ g4z = (const float4*)gz  + (base >> 2);
            const float4* __restrict__ g4b = (const float4*)gb2 + (base >> 2);
            #pragma unroll
            for (int t = threadIdx.x; t < TS / 4; t += BLOCK) {
                const float4 vx = g4x[t];
                const float4 vy = g4y[t];
                const float4 vz = g4z[t];
                const float4 vb = g4b[t];
                const int chunk = t >> 4;
                const int pa = (2 * t) & 31;                 // even, <= 30
                const int ia = (chunk << 5) | ((pa + chunk) & 31);
                const int ib = (chunk << 5) | ((pa + 1 + chunk) & 31);
                shX[ia] = make_float2(vx.x, vx.y);  shX[ib] = make_float2(vx.z, vx.w);
                shY[ia] = make_float2(vy.x, vy.y);  shY[ib] = make_float2(vy.z, vy.w);
                shZ[ia] = make_float2(vz.x, vz.y);  shZ[ib] = make_float2(vz.z, vz.w);
                shB[ia] = make_float2(vb.x, vb.y);  shB[ib] = make_float2(vb.z, vb.w);
            }
        }
        __syncthreads();

        // Lane owns chunk == lane: points [base + lane*64, +64), read via rotation.
        const int cb = lane << 5;
        #pragma unroll 8
        for (int v = 0; v < 32; v++) {
            const int idx = cb | ((v + lane) & 31);
            const unsigned long long xp  = *reinterpret_cast<const unsigned long long*>(&shX[idx]);
            const unsigned long long yp  = *reinterpret_cast<const unsigned long long*>(&shY[idx]);
            const unsigned long long zp  = *reinterpret_cast<const unsigned long long*>(&shZ[idx]);
            const unsigned long long b2p = *reinterpret_cast<const unsigned long long*>(&shB[idx]);
            #pragma unroll
            for (int q = 0; q < QPW; q++) {
                unsigned long long acc, dot2, d2v;
                MUL2(acc, zp, qz2[q]);
                FMA2(dot2, yp, qy2[q], acc);
                FMA2(dot2, xp, qx2[q], dot2);
                ADD2(acc, qa22[q], b2p);
                FMA2(d2v, NEG2, dot2, acc);
                float dlo, dhi;
                UNPACK2(dlo, dhi, d2v);
                dlo1[q] = fminf(dlo1[q], dlo);
                dhi1[q] = fminf(dhi1[q], dhi);
            }
        }
    }

    // ---- Epilogue per query: recover exact stable top-2 indices ----
    #pragma unroll 1
    for (int q = 0; q < QPW; q++) {
        const int qi = qbase + q;
        const float qx = qc[qi * 3 + 0];
        const float qy = qc[qi * 3 + 1];
        const float qz = qc[qi * 3 + 2];
        const float a2 = sqnorm3(qx, qy, qz);

        const float lmin = fminf(dlo1[q], dhi1[q]);

        // Warp top-2 VALUES (with multiplicity): bd <= sd
        float bd = lmin, sd = FLT_MAX;
        #pragma unroll
        for (int off = 16; off > 0; off >>= 1) {
            const float ob = __shfl_xor_sync(0xFFFFFFFFu, bd, off);
            const float os = __shfl_xor_sync(0xFFFFFFFFu, sd, off);
            const float nb = fminf(bd, ob);
            const float mx = fmaxf(bd, ob);
            sd = fminf(mx, fminf(sd, os));
            bd = nb;
        }
        // Any lane holding a global top-2 point has lane-min in {bd, sd}:
        // nothing lies strictly between bd and sd by sd's definition.
        unsigned mask = __ballot_sync(0xFFFFFFFFu, lmin == bd || lmin == sd);

        float g1d = FLT_MAX, g2d = FLT_MAX;
        int   g1i = 0x7fffffff, g2i = 0x7fffffff;

        while (mask) {
            const int W = __ffs(mask) - 1;
            mask &= mask - 1;

            // Cooperative, COALESCED rescan of chunk W: 16 tiles x 64 contiguous pts.
            float p1d = FLT_MAX, p2d = FLT_MAX;
            int   p1i = 0x7fffffff, p2i = 0x7fffffff;
            #pragma unroll 4
            for (int r = 0; r < NT; r++) {
                const int nb0 = r * TS + W * 64;
                #pragma unroll
                for (int round = 0; round < 2; round++) {
                    const int n = nb0 + round * 32 + lane;   // per-lane ascending order
                    const float d = dist_d(gx[n], gy[n], gz[n], gb2[n], qx, qy, qz, a2);
                    const bool lt1 = d < p1d;
                    const bool lt2 = d < p2d;
                    p2d = lt1 ? p1d : (lt2 ? d : p2d);
                    p2i = lt1 ? p1i : (lt2 ? n : p2i);
                    p1d = lt1 ? d   : p1d;
                    p1i = lt1 ? n   : p1i;
                }
            }
            // Lex merge of per-lane top-2 lists
            #pragma unroll
            for (int off = 16; off > 0; off >>= 1) {
                const float o1d = __shfl_xor_sync(0xFFFFFFFFu, p1d, off);
                const float o2d = __shfl_xor_sync(0xFFFFFFFFu, p2d, off);
                const int   o1i = __shfl_xor_sync(0xFFFFFFFFu, p1i, off);
                const int   o2i = __shfl_xor_sync(0xFFFFFFFFu, p2i, off);
                const bool aF = lex_lt(p1d, p1i, o1d, o1i);
                const float c1 = aF ? o1d : p1d;  const int c1i = aF ? o1i : p1i;
                const float c2 = aF ? p2d : o2d;  const int c2i = aF ? p2i : o2i;
                const float n1 = aF ? p1d : o1d;  const int n1i = aF ? p1i : o1i;
                const bool t1 = lex_lt(c1, c1i, c2, c2i);
                p1d = n1; p1i = n1i;
                p2d = t1 ? c1 : c2; p2i = t1 ? c1i : c2i;
            }
            const float w1d = __shfl_sync(0xFFFFFFFFu, p1d, 0);
            const int   w1i = __shfl_sync(0xFFFFFFFFu, p1i, 0);
            const float w2d = __shfl_sync(0xFFFFFFFFu, p2d, 0);
            const int   w2i = __shfl_sync(0xFFFFFFFFu, p2i, 0);

            // Merge (g1,g2) with (w1,w2) — both lex-sorted top-2 of disjoint sets
            const bool aF = lex_lt(g1d, g1i, w1d, w1i);
            const float c1 = aF ? w1d : g1d;  const int c1i = aF ? w1i : g1i;
            const float c2 = aF ? g2d : w2d;  const int c2i = aF ? g2i : w2i;
            const float n1 = aF ? g1d : w1d;  const int n1i = aF ? g1i : w1i;
            const bool t1 = lex_lt(c1, c1i, c2, c2i);
            g1d = n1; g1i = n1i;
            g2d = t1 ? c1 : c2; g2i = t1 ? c1i : c2i;
        }

        const int sel = g2i;   // stable 2nd-nearest index

        // Gather feature row (256 floats), warp-coalesced
        const float4* __restrict__ srow = reinterpret_cast<const float4*>(feats + (size_t)sel * PC);
        float4* __restrict__ drow = reinterpret_cast<float4*>(out_side + (size_t)qi * PC);
        #pragma unroll
        for (int k = lane; k < PC / 4; k += 32) {
            drow[k] = srow[k];
        }
    }
}

extern "C" void kernel_launch(void* const* d_in, const int* in_sizes, int n_in,
                              void* d_out, int out_size)
{
    const float* src        = (const float*)d_in[0];
    const float* tgt        = (const float*)d_in[1];
    const float* src_coords = (const float*)d_in[2];
    const float* tgt_coords = (const float*)d_in[3];
    const float* src_sc     = (const float*)d_in[4];
    const float* tgt_sc     = (const float*)d_in[5];
    float* out = (float*)d_out;

    dim3 pgrid(PN / 256, 2);
    pack_kernel<<<pgrid, 256>>>(src_coords, tgt_coords);

    dim3 grid(PM / QPB, 2);
    closest_pool_main<<<grid, BLOCK>>>(src, tgt, src_sc, tgt_sc, out);
}

// round 10
// speedup vs baseline: 2.0917x; 1.0319x over previous
#include <cuda_runtime.h>
#include <float.h>
#include <stdint.h>

// Problem constants
#define PN 32768   // points per side
#define PM 8192    // shortcut (query) points per side
#define PC 256     // feature channels

#define TS 2048          // tile points in smem
#define NT (PN / TS)     // 16 tiles
#define WARPS 8
#define QPW 2            // queries per warp (occupancy knob: 16384/QPW warps total)
#define BLOCK (WARPS * 32)
#define QPB (WARPS * QPW)   // 16 queries per block

// Pair-interleaved packed coords: A = (x0,x1,y0,y1), B = (z0,z1,b20,b21) per point pair.
// b2 computed once; main loop and rescan read identical bits.
__device__ float4 g_A[2][PN / 2];
__device__ float4 g_B[2][PN / 2];

__forceinline__ __device__ float sqnorm3(float x, float y, float z) {
    return (x * x + y * y) + z * z;
}

// Scalar distance — bit-identical to the packed f32x2 path (IEEE per-component),
// same sequence as the R1 kernel that measured rel_err == 0.0.
__forceinline__ __device__ float dist_d(float x, float y, float z, float b2,
                                        float qx, float qy, float qz, float a2) {
    const float dot = fmaf(x, qx, fmaf(y, qy, z * qz));
    const float t   = a2 + b2;
    return fmaf(-2.0f, dot, t);
}

// Packed f32x2 ops (sm_103a)
#define FMA2(r, a, b, c) asm("fma.rn.f32x2 %0, %1, %2, %3;" : "=l"(r) : "l"(a), "l"(b), "l"(c))
#define MUL2(r, a, b)    asm("mul.rn.f32x2 %0, %1, %2;"     : "=l"(r) : "l"(a), "l"(b))
#define ADD2(r, a, b)    asm("add.rn.f32x2 %0, %1, %2;"     : "=l"(r) : "l"(a), "l"(b))
#define PACK2(r, lo, hi) asm("mov.b64 %0, {%1, %2};" : "=l"(r) : "f"(lo), "f"(hi))
#define UNPACK2(lo, hi, r) asm("mov.b64 {%0, %1}, %2;" : "=f"(lo), "=f"(hi) : "l"(r))

__forceinline__ __device__ bool lex_lt(float da, int ia, float db, int ib) {
    return (da < db) || (da == db && ia < ib);
}

__global__ void pack_kernel(const float* __restrict__ src_coords,
                            const float* __restrict__ tgt_coords) {
    const int p = blockIdx.x * blockDim.x + threadIdx.x;   // point-pair index
    const int side = blockIdx.y;
    const float* __restrict__ c = side ? tgt_coords : src_coords;
    const int n0 = 2 * p;
    const float x0 = c[n0 * 3 + 0], y0 = c[n0 * 3 + 1], z0 = c[n0 * 3 + 2];
    const float x1 = c[n0 * 3 + 3], y1 = c[n0 * 3 + 4], z1 = c[n0 * 3 + 5];
    g_A[side][p] = make_float4(x0, x1, y0, y1);
    g_B[side][p] = make_float4(z0, z1, sqnorm3(x0, y0, z0), sqnorm3(x1, y1, z1));
}

__global__ __launch_bounds__(BLOCK, 5) void closest_pool_main(
    const float* __restrict__ src_feats,
    const float* __restrict__ tgt_feats,
    const float* __restrict__ src_sc,
    const float* __restrict__ tgt_sc,
    float* __restrict__ out)
{
    // Chunk-contiguous tiles with rotation swizzle:
    // logical (chunk c, slot s) -> physical c*32 + ((s + c) & 31); slot = 2 points (float4).
    __shared__ __align__(16) float4 shA[TS / 2];
    __shared__ __align__(16) float4 shB[TS / 2];

    const int side = blockIdx.y;
    const float* __restrict__ feats = side ? tgt_feats : src_feats;
    const float* __restrict__ qc    = side ? tgt_sc    : src_sc;
    float* __restrict__ out_side = out + (size_t)side * PM * PC;

    const float4* __restrict__ gA = g_A[side];
    const float4* __restrict__ gB = g_B[side];

    const int warp = threadIdx.x >> 5;
    const int lane = threadIdx.x & 31;
    const int qbase = blockIdx.x * QPB + warp * QPW;

    // Packed query broadcasts (scalars reloaded in epilogue to save regs)
    unsigned long long qx2[QPW], qy2[QPW], qz2[QPW], qa22[QPW];
    #pragma unroll
    for (int q = 0; q < QPW; q++) {
        const int qi = qbase + q;
        const float qx = qc[qi * 3 + 0];
        const float qy = qc[qi * 3 + 1];
        const float qz = qc[qi * 3 + 2];
        const float a2 = sqnorm3(qx, qy, qz);
        PACK2(qx2[q], qx, qx);
        PACK2(qy2[q], qy, qy);
        PACK2(qz2[q], qz, qz);
        PACK2(qa22[q], a2, a2);
    }
    unsigned long long NEG2;
    { const float m2 = -2.0f; PACK2(NEG2, m2, m2); }

    // Value-only per-lane minima (order-free; indices recovered in epilogue)
    float dlo1[QPW], dhi1[QPW];
    #pragma unroll
    for (int q = 0; q < QPW; q++) { dlo1[q] = FLT_MAX; dhi1[q] = FLT_MAX; }

    for (int base = 0; base < PN; base += TS) {
        __syncthreads();
        // Fill: coalesced float4 loads, rotation-swizzled float4 stores.
        {
            const int g0 = base >> 1;              // float4 index of tile start
            #pragma unroll
            for (int t = threadIdx.x; t < TS / 2; t += BLOCK) {
                const float4 va = gA[g0 + t];
                const float4 vb = gB[g0 + t];
                const int chunk = t >> 5;          // 32 slots (64 pts) per chunk
                const int slot  = t & 31;
                const int ph = (chunk << 5) | ((slot + chunk) & 31);
                shA[ph] = va;
                shB[ph] = vb;
            }
        }
        __syncthreads();

        // Lane owns chunk == lane: points [base + lane*64, +64).
        const int cb = lane << 5;
        #pragma unroll 8
        for (int v = 0; v < 32; v++) {
            const int idx = cb | ((v + lane) & 31);
            const float4 va = shA[idx];            // (x0,x1,y0,y1)
            const float4 vb = shB[idx];            // (z0,z1,b20,b21)
            unsigned long long xp, yp, zp, b2p;
            PACK2(xp,  va.x, va.y);
            PACK2(yp,  va.z, va.w);
            PACK2(zp,  vb.x, vb.y);
            PACK2(b2p, vb.z, vb.w);
            #pragma unroll
            for (int q = 0; q < QPW; q++) {
                unsigned long long acc, dot2, d2v;
                MUL2(acc, zp, qz2[q]);
                FMA2(dot2, yp, qy2[q], acc);
                FMA2(dot2, xp, qx2[q], dot2);
                ADD2(acc, qa22[q], b2p);
                FMA2(d2v, NEG2, dot2, acc);
                float dlo, dhi;
                UNPACK2(dlo, dhi, d2v);
                dlo1[q] = fminf(dlo1[q], dlo);
                dhi1[q] = fminf(dhi1[q], dhi);
            }
        }
    }

    // ---- Epilogue per query: recover exact stable top-2 indices ----
    #pragma unroll 1
    for (int q = 0; q < QPW; q++) {
        const int qi = qbase + q;
        const float qx = qc[qi * 3 + 0];
        const float qy = qc[qi * 3 + 1];
        const float qz = qc[qi * 3 + 2];
        const float a2 = sqnorm3(qx, qy, qz);

        const float lmin = fminf(dlo1[q], dhi1[q]);

        // Warp top-2 VALUES with multiplicity: bd <= sd
        float bd = lmin, sd = FLT_MAX;
        #pragma unroll
        for (int off = 16; off > 0; off >>= 1) {
            const float ob = __shfl_xor_sync(0xFFFFFFFFu, bd, off);
            const float os = __shfl_xor_sync(0xFFFFFFFFu, sd, off);
            const float nb = fminf(bd, ob);
            const float mx = fmaxf(bd, ob);
            sd = fminf(mx, fminf(sd, os));
            bd = nb;
        }
        // Lanes holding a global top-2 point have lane-min in {bd, sd}
        // (nothing lies strictly between bd and sd by sd's definition).
        unsigned mask = __ballot_sync(0xFFFFFFFFu, lmin == bd || lmin == sd);

        float g1d = FLT_MAX, g2d = FLT_MAX;
        int   g1i = 0x7fffffff, g2i = 0x7fffffff;

        while (mask) {
            const int W = __ffs(mask) - 1;
            mask &= mask - 1;

            // Cooperative coalesced rescan of chunk W: 16 tiles x 64 contiguous pts,
            // 2 points per lane from the packed pair arrays (identical bits).
            float p1d = FLT_MAX, p2d = FLT_MAX;
            int   p1i = 0x7fffffff, p2i = 0x7fffffff;
            #pragma unroll 4
            for (int r = 0; r < NT; r++) {
                const int pbase = (r * TS + W * 64) >> 1;   // float4 index
                const float4 va = gA[pbase + lane];
                const float4 vb = gB[pbase + lane];
                const int n0 = r * TS + W * 64 + 2 * lane;
                // lo point then hi point — per-lane ascending order (stability)
                {
                    const float d = dist_d(va.x, va.z, vb.x, vb.z, qx, qy, qz, a2);
                    const bool lt1 = d < p1d;
                    const bool lt2 = d < p2d;
                    p2d = lt1 ? p1d : (lt2 ? d : p2d);
                    p2i = lt1 ? p1i : (lt2 ? n0 : p2i);
                    p1d = lt1 ? d   : p1d;
                    p1i = lt1 ? n0  : p1i;
                }
                {
                    const int n1 = n0 + 1;
                    const float d = dist_d(va.y, va.w, vb.y, vb.w, qx, qy, qz, a2);
                    const bool lt1 = d < p1d;
                    const bool lt2 = d < p2d;
                    p2d = lt1 ? p1d : (lt2 ? d : p2d);
                    p2i = lt1 ? p1i : (lt2 ? n1 : p2i);
                    p1d = lt1 ? d   : p1d;
                    p1i = lt1 ? n1  : p1i;
                }
            }
            // Lex merge of per-lane top-2 lists
            #pragma unroll
            for (int off = 16; off > 0; off >>= 1) {
                const float o1d = __shfl_xor_sync(0xFFFFFFFFu, p1d, off);
                const float o2d = __shfl_xor_sync(0xFFFFFFFFu, p2d, off);
                const int   o1i = __shfl_xor_sync(0xFFFFFFFFu, p1i, off);
                const int   o2i = __shfl_xor_sync(0xFFFFFFFFu, p2i, off);
                const bool aF = lex_lt(p1d, p1i, o1d, o1i);
                const float c1 = aF ? o1d : p1d;  const int c1i = aF ? o1i : p1i;
                const float c2 = aF ? p2d : o2d;  const int c2i = aF ? p2i : o2i;
                const float n1 = aF ? p1d : o1d;  const int n1i = aF ? p1i : o1i;
                const bool t1 = lex_lt(c1, c1i, c2, c2i);
                p1d = n1; p1i = n1i;
                p2d = t1 ? c1 : c2; p2i = t1 ? c1i : c2i;
            }
            const float w1d = __shfl_sync(0xFFFFFFFFu, p1d, 0);
            const int   w1i = __shfl_sync(0xFFFFFFFFu, p1i, 0);
            const float w2d = __shfl_sync(0xFFFFFFFFu, p2d, 0);
            const int   w2i = __shfl_sync(0xFFFFFFFFu, p2i, 0);

            // Merge disjoint-set top-2 lists
            const bool aF = lex_lt(g1d, g1i, w1d, w1i);
            const float c1 = aF ? w1d : g1d;  const int c1i = aF ? w1i : g1i;
            const float c2 = aF ? g2d : w2d;  const int c2i = aF ? g2i : w2i;
            const float n1 = aF ? g1d : w1d;  const int n1i = aF ? g1i : w1i;
            const bool t1 = lex_lt(c1, c1i, c2, c2i);
            g1d = n1; g1i = n1i;
            g2d = t1 ? c1 : c2; g2i = t1 ? c1i : c2i;
        }

        const int sel = g2i;   // stable 2nd-nearest index

        // Gather feature row (256 floats), warp-coalesced
        const float4* __restrict__ srow = reinterpret_cast<const float4*>(feats + (size_t)sel * PC);
        float4* __restrict__ drow = reinterpret_cast<float4*>(out_side + (size_t)qi * PC);
        #pragma unroll
        for (int k = lane; k < PC / 4; k += 32) {
            drow[k] = srow[k];
        }
    }
}

extern "C" void kernel_launch(void* const* d_in, const int* in_sizes, int n_in,
                              void* d_out, int out_size)
{
    const float* src        = (const float*)d_in[0];
    const float* tgt        = (const float*)d_in[1];
    const float* src_coords = (const float*)d_in[2];
    const float* tgt_coords = (const float*)d_in[3];
    const float* src_sc     = (const float*)d_in[4];
    const float* tgt_sc     = (const float*)d_in[5];
    float* out = (float*)d_out;

    dim3 pgrid(PN / 2 / 256, 2);
    pack_kernel<<<pgrid, 256>>>(src_coords, tgt_coords);

    dim3 grid(PM / QPB, 2);
    closest_pool_main<<<grid, BLOCK>>>(src, tgt, src_sc, tgt_sc, out);
}